// round 5
// baseline (speedup 1.0000x reference)
#include <cuda_runtime.h>
#include <cuda_fp16.h>
#include <cstdint>

#define NN 100000
#define NE 1600000
#define DD 128
#define LL 3

// ---------------- device scratch ----------------
__device__ __half   g_hA[(size_t)NN * DD];
__device__ __half   g_hB[(size_t)NN * DD];
__device__ uint32_t g_S[(size_t)NN * DD];   // aggregated features, tf32 bit pattern
__device__ float    g_inv[NN];
__device__ int      g_deg[NN];
__device__ int      g_off[NN + 1];
__device__ int      g_cur[NN];
__device__ int      g_csr[NE];

__device__ __forceinline__ uint32_t f2tf32(float f) {
    uint32_t u;
    asm("cvt.rna.tf32.f32 %0, %1;" : "=r"(u) : "f"(f));
    return u;
}

// ---------------- setup: hA = (half)emb[annotation], zero deg ----------------
__global__ void k_init(const int* __restrict__ ann, const float* __restrict__ emb) {
    int t = blockIdx.x * blockDim.x + threadIdx.x;
    if (t < NN * 32) {
        int v = t >> 5, q = t & 31;
        int a = ann[v];
        float4 val = ((const float4*)emb)[(size_t)a * 32 + q];
        uint2 o;
        __half2 h01 = __floats2half2_rn(val.x, val.y);
        __half2 h23 = __floats2half2_rn(val.z, val.w);
        o.x = *(uint32_t*)&h01; o.y = *(uint32_t*)&h23;
        ((uint2*)g_hA)[t] = o;
    }
    if (t < NN) g_deg[t] = 0;
}

// ---------------- degree count ----------------
__global__ void k_count(const int* __restrict__ dst) {
    int e = blockIdx.x * blockDim.x + threadIdx.x;
    if (e < NE) atomicAdd(&g_deg[dst[e]], 1);
}

// ---------------- single-block scan ----------------
__global__ void __launch_bounds__(1024) k_scan() {
    const int PER = (NN + 1023) / 1024;     // 98
    int t = threadIdx.x;
    int lo = t * PER;
    int hi = lo + PER; if (hi > NN) hi = NN;
    int s = 0;
    for (int i = lo; i < hi; i++) s += g_deg[i];

    int lane = t & 31, w = t >> 5;
    int v = s;
    #pragma unroll
    for (int o = 1; o < 32; o <<= 1) {
        int u = __shfl_up_sync(0xffffffffu, v, o);
        if (lane >= o) v += u;
    }
    __shared__ int ws[32];
    if (lane == 31) ws[w] = v;
    __syncthreads();
    if (w == 0) {
        int x = ws[lane];
        #pragma unroll
        for (int o = 1; o < 32; o <<= 1) {
            int u = __shfl_up_sync(0xffffffffu, x, o);
            if (lane >= o) x += u;
        }
        ws[lane] = x;
    }
    __syncthreads();
    int ex = v - s + (w > 0 ? ws[w - 1] : 0);

    int run = ex;
    for (int i = lo; i < hi; i++) {
        int d = g_deg[i];
        g_off[i] = run;
        g_cur[i] = run;
        g_inv[i] = 1.0f / (float)(d + 1);
        run += d;
    }
    if (hi == NN && lo < NN) g_off[NN] = run;
}

// ---------------- scatter edges into CSR ----------------
__global__ void k_scatter(const int* __restrict__ src, const int* __restrict__ dst) {
    int e = blockIdx.x * blockDim.x + threadIdx.x;
    if (e < NE) {
        int d = dst[e];
        int p = atomicAdd(&g_cur[d], 1);
        g_csr[p] = src[e];
    }
}

// ---------------- SAGE aggregation: warp per node, 8-edge batches for MLP ----------------
__global__ void __launch_bounds__(256) k_sage(const __half* __restrict__ hin) {
    int gt = blockIdx.x * blockDim.x + threadIdx.x;
    int v = gt >> 5;
    if (v >= NN) return;
    int lane = gt & 31;
    const uint2* h2 = (const uint2*)hin;

    uint2 sv = h2[(size_t)v * 32 + lane];
    float2 f01 = __half22float2(*(__half2*)&sv.x);
    float2 f23 = __half22float2(*(__half2*)&sv.y);
    float4 acc = make_float4(f01.x, f01.y, f23.x, f23.y);

    int s = g_off[v], e = g_off[v + 1];
    for (int i = s; i < e; i += 8) {
        // 8 independent index loads (tail slots clamped to e-1)
        int u[8];
        #pragma unroll
        for (int j = 0; j < 8; j++) {
            int k = i + j;
            u[j] = __ldg(&g_csr[k < e ? k : e - 1]);
        }
        // 8 independent row loads
        uint2 x[8];
        #pragma unroll
        for (int j = 0; j < 8; j++)
            x[j] = h2[(size_t)u[j] * 32 + lane];
        // predicated accumulation (tail slots skipped)
        #pragma unroll
        for (int j = 0; j < 8; j++) {
            if (i + j < e) {
                float2 a01 = __half22float2(*(__half2*)&x[j].x);
                float2 a23 = __half22float2(*(__half2*)&x[j].y);
                acc.x += a01.x; acc.y += a01.y; acc.z += a23.x; acc.w += a23.y;
            }
        }
    }

    float iv = g_inv[v];
    uint4 r;
    r.x = f2tf32(acc.x * iv); r.y = f2tf32(acc.y * iv);
    r.z = f2tf32(acc.z * iv); r.w = f2tf32(acc.w * iv);
    ((uint4*)g_S)[(size_t)v * 32 + lane] = r;
}

// ---------------- tf32 MMA GEMM: hout = relu(S @ W + b) ----------------
#define APITCH 132
#define BPITCH 136
#define GSMEM ((128 * APITCH + 128 * BPITCH) * 4)

__global__ void __launch_bounds__(256) k_mma(__half* __restrict__ hout_h,
                                             float* __restrict__ out_f,
                                             const float* __restrict__ W,
                                             const float* __restrict__ bias) {
    extern __shared__ uint32_t sm[];
    uint32_t* As = sm;                 // [128][APITCH]
    uint32_t* Bs = sm + 128 * APITCH;  // [128][BPITCH], Bs[k][n]
    int tid = threadIdx.x;
    int lane = tid & 31, w = tid >> 5;
    int m0 = blockIdx.x * 128;

    #pragma unroll
    for (int t = 0; t < 16; t++) {
        int q = tid + t * 256;
        int r = q >> 5, c4 = (q & 31) * 4;
        uint4 av;
        if (m0 + r < NN) av = ((const uint4*)g_S)[(size_t)(m0 + r) * 32 + (q & 31)];
        else             av = make_uint4(0u, 0u, 0u, 0u);
        *(uint4*)&As[r * APITCH + c4] = av;
        float4 wv = ((const float4*)W)[q];
        uint32_t* p = &Bs[r * BPITCH + c4];
        p[0] = f2tf32(wv.x); p[1] = f2tf32(wv.y); p[2] = f2tf32(wv.z); p[3] = f2tf32(wv.w);
    }
    __syncthreads();

    int warp_m = w >> 1;
    int warp_n = w & 1;
    int g = lane >> 2;
    int tg = lane & 3;

    float acc[2][8][4];
    #pragma unroll
    for (int mi = 0; mi < 2; mi++)
        #pragma unroll
        for (int ni = 0; ni < 8; ni++)
            #pragma unroll
            for (int c = 0; c < 4; c++) acc[mi][ni][c] = 0.f;

    #pragma unroll
    for (int kc = 0; kc < 16; kc++) {
        int k0 = kc * 8;
        uint32_t a[2][4];
        #pragma unroll
        for (int mi = 0; mi < 2; mi++) {
            int r = warp_m * 32 + mi * 16 + g;
            a[mi][0] = As[r * APITCH + k0 + tg];
            a[mi][1] = As[(r + 8) * APITCH + k0 + tg];
            a[mi][2] = As[r * APITCH + k0 + tg + 4];
            a[mi][3] = As[(r + 8) * APITCH + k0 + tg + 4];
        }
        #pragma unroll
        for (int ni = 0; ni < 8; ni++) {
            int cn = warp_n * 64 + ni * 8 + g;
            uint32_t b0 = Bs[(k0 + tg) * BPITCH + cn];
            uint32_t b1 = Bs[(k0 + tg + 4) * BPITCH + cn];
            #pragma unroll
            for (int mi = 0; mi < 2; mi++) {
                asm volatile(
                    "mma.sync.aligned.m16n8k8.row.col.f32.tf32.tf32.f32 "
                    "{%0,%1,%2,%3}, {%4,%5,%6,%7}, {%8,%9}, {%0,%1,%2,%3};"
                    : "+f"(acc[mi][ni][0]), "+f"(acc[mi][ni][1]),
                      "+f"(acc[mi][ni][2]), "+f"(acc[mi][ni][3])
                    : "r"(a[mi][0]), "r"(a[mi][1]), "r"(a[mi][2]), "r"(a[mi][3]),
                      "r"(b0), "r"(b1));
            }
        }
    }

    #pragma unroll
    for (int ni = 0; ni < 8; ni++) {
        int col = warp_n * 64 + ni * 8 + 2 * tg;
        float b0 = bias[col], b1 = bias[col + 1];
        #pragma unroll
        for (int mi = 0; mi < 2; mi++) {
            int row = m0 + warp_m * 32 + mi * 16 + g;
            float v00 = fmaxf(acc[mi][ni][0] + b0, 0.f);
            float v01 = fmaxf(acc[mi][ni][1] + b1, 0.f);
            float v10 = fmaxf(acc[mi][ni][2] + b0, 0.f);
            float v11 = fmaxf(acc[mi][ni][3] + b1, 0.f);
            if (out_f) {
                if (row < NN)     { float2 r0 = {v00, v01}; *(float2*)&out_f[(size_t)row * DD + col] = r0; }
                if (row + 8 < NN) { float2 r1 = {v10, v11}; *(float2*)&out_f[(size_t)(row + 8) * DD + col] = r1; }
            } else {
                if (row < NN)     *(__half2*)&hout_h[(size_t)row * DD + col] = __floats2half2_rn(v00, v01);
                if (row + 8 < NN) *(__half2*)&hout_h[(size_t)(row + 8) * DD + col] = __floats2half2_rn(v10, v11);
            }
        }
    }
}

// ---------------- launcher ----------------
extern "C" void kernel_launch(void* const* d_in, const int* in_sizes, int n_in,
                              void* d_out, int out_size) {
    const int*   ann = (const int*)d_in[0];
    const int*   src = (const int*)d_in[1];
    const int*   dst = (const int*)d_in[2];
    const float* emb = (const float*)d_in[3];
    const float* Ws  = (const float*)d_in[4];
    const float* bs  = (const float*)d_in[5];
    float*       out = (float*)d_out;

    cudaFuncSetAttribute(k_mma, cudaFuncAttributeMaxDynamicSharedMemorySize, GSMEM);

    k_init   <<<(NN * 32 + 255) / 256, 256>>>(ann, emb);
    k_count  <<<(NE + 255) / 256, 256>>>(dst);
    k_scan   <<<1, 1024>>>();
    k_scatter<<<(NE + 255) / 256, 256>>>(src, dst);

    __half* hA; __half* hB;
    cudaGetSymbolAddress((void**)&hA, g_hA);
    cudaGetSymbolAddress((void**)&hB, g_hB);

    int grid = (NN + 127) / 128;  // 782
    k_sage<<<(NN * 32 + 255) / 256, 256>>>(hA);
    k_mma <<<grid, 256, GSMEM>>>(hB, nullptr, Ws + 0 * DD * DD, bs + 0 * DD);
    k_sage<<<(NN * 32 + 255) / 256, 256>>>(hB);
    k_mma <<<grid, 256, GSMEM>>>(hA, nullptr, Ws + 1 * DD * DD, bs + 1 * DD);
    k_sage<<<(NN * 32 + 255) / 256, 256>>>(hA);
    k_mma <<<grid, 256, GSMEM>>>(nullptr, out, Ws + 2 * DD * DD, bs + 2 * DD);
}

// round 6
// speedup vs baseline: 1.0170x; 1.0170x over previous
#include <cuda_runtime.h>
#include <cuda_fp16.h>
#include <cstdint>

#define NN 100000
#define NE 1600000
#define DD 128
#define LL 3

// ---------------- device scratch ----------------
__device__ __half   g_hA[(size_t)NN * DD];
__device__ __half   g_hB[(size_t)NN * DD];
__device__ __half   g_S[(size_t)NN * DD];   // aggregated features (fp16)
__device__ float    g_inv[NN];
__device__ int      g_deg[NN];              // zero-initialized; re-zeroed by k_scan each call
__device__ int      g_off[NN + 1];
__device__ int      g_cur[NN];
__device__ int      g_csr[NE];

// ---------------- setup: hA = (half)emb[annotation]  +  degree count ----------------
__global__ void k_setup(const int* __restrict__ ann, const float* __restrict__ emb,
                        const int* __restrict__ dst) {
    int t = blockIdx.x * blockDim.x + threadIdx.x;
    if (t < NN * 32) {
        int v = t >> 5, q = t & 31;
        int a = ann[v];
        float4 val = ((const float4*)emb)[(size_t)a * 32 + q];
        uint2 o;
        __half2 h01 = __floats2half2_rn(val.x, val.y);
        __half2 h23 = __floats2half2_rn(val.z, val.w);
        o.x = *(uint32_t*)&h01; o.y = *(uint32_t*)&h23;
        ((uint2*)g_hA)[t] = o;
    }
    if (t < NE) atomicAdd(&g_deg[dst[t]], 1);
}

// ---------------- single-block scan (consumes deg, re-zeros it for next replay) ----------------
__global__ void __launch_bounds__(1024) k_scan() {
    const int PER = (NN + 1023) / 1024;     // 98
    int t = threadIdx.x;
    int lo = t * PER;
    int hi = lo + PER; if (hi > NN) hi = NN;
    int s = 0;
    for (int i = lo; i < hi; i++) s += g_deg[i];

    int lane = t & 31, w = t >> 5;
    int v = s;
    #pragma unroll
    for (int o = 1; o < 32; o <<= 1) {
        int u = __shfl_up_sync(0xffffffffu, v, o);
        if (lane >= o) v += u;
    }
    __shared__ int ws[32];
    if (lane == 31) ws[w] = v;
    __syncthreads();
    if (w == 0) {
        int x = ws[lane];
        #pragma unroll
        for (int o = 1; o < 32; o <<= 1) {
            int u = __shfl_up_sync(0xffffffffu, x, o);
            if (lane >= o) x += u;
        }
        ws[lane] = x;
    }
    __syncthreads();
    int ex = v - s + (w > 0 ? ws[w - 1] : 0);

    int run = ex;
    for (int i = lo; i < hi; i++) {
        int d = g_deg[i];
        g_off[i] = run;
        g_cur[i] = run;
        g_inv[i] = 1.0f / (float)(d + 1);
        g_deg[i] = 0;                       // restore invariant for next call
        run += d;
    }
    if (hi == NN && lo < NN) g_off[NN] = run;
}

// ---------------- scatter edges into CSR ----------------
__global__ void k_scatter(const int* __restrict__ src, const int* __restrict__ dst) {
    int e = blockIdx.x * blockDim.x + threadIdx.x;
    if (e < NE) {
        int d = dst[e];
        int p = atomicAdd(&g_cur[d], 1);
        g_csr[p] = src[e];
    }
}

// ---------------- SAGE aggregation: warp per node, fp16 in/out, fp32 accum ----------------
__global__ void __launch_bounds__(256) k_sage(const __half* __restrict__ hin) {
    int gt = blockIdx.x * blockDim.x + threadIdx.x;
    int v = gt >> 5;
    if (v >= NN) return;
    int lane = gt & 31;
    const uint2* h2 = (const uint2*)hin;

    uint2 sv = h2[(size_t)v * 32 + lane];
    float2 f01 = __half22float2(*(__half2*)&sv.x);
    float2 f23 = __half22float2(*(__half2*)&sv.y);
    float4 acc = make_float4(f01.x, f01.y, f23.x, f23.y);

    int s = g_off[v], e = g_off[v + 1];
    for (int i = s; i < e; i++) {
        int u = __ldg(&g_csr[i]);
        uint2 xv = h2[(size_t)u * 32 + lane];
        float2 x01 = __half22float2(*(__half2*)&xv.x);
        float2 x23 = __half22float2(*(__half2*)&xv.y);
        acc.x += x01.x; acc.y += x01.y; acc.z += x23.x; acc.w += x23.y;
    }
    float iv = g_inv[v];
    uint2 r;
    __half2 r01 = __floats2half2_rn(acc.x * iv, acc.y * iv);
    __half2 r23 = __floats2half2_rn(acc.z * iv, acc.w * iv);
    r.x = *(uint32_t*)&r01; r.y = *(uint32_t*)&r23;
    ((uint2*)g_S)[(size_t)v * 32 + lane] = r;
}

// ---------------- fp16 MMA GEMM: hout = relu(S @ W + b) ----------------
// As: [128 m][136 halves] row-major (k contiguous); Bs: [128 n][136 halves] (k contiguous, = W^T)
#define HP 136
#define GSMEM (2 * 128 * HP * 2)

__global__ void __launch_bounds__(256, 2) k_mma(__half* __restrict__ hout_h,
                                                float* __restrict__ out_f,
                                                const float* __restrict__ W,
                                                const float* __restrict__ bias) {
    extern __shared__ __half sm[];
    __half* As = sm;             // [128][HP]
    __half* Bs = sm + 128 * HP;  // [128][HP]
    int tid = threadIdx.x;
    int lane = tid & 31, w = tid >> 5;
    int m0 = blockIdx.x * 128;

    // fill A: 2048 uint4 (8 halves each)
    #pragma unroll
    for (int t = 0; t < 8; t++) {
        int q = tid + t * 256;            // 0..2047
        int r = q >> 4, c8 = (q & 15) * 8;
        uint4 av;
        if (m0 + r < NN) av = ((const uint4*)g_S)[(size_t)(m0 + r) * 16 + (q & 15)];
        else             av = make_uint4(0u, 0u, 0u, 0u);
        *(uint4*)&As[r * HP + c8] = av;
    }
    // fill B transposed: Bs[n][k] = (half)W[k][n]
    #pragma unroll
    for (int t = 0; t < 16; t++) {
        int q = tid + t * 256;            // 0..4095
        int k = q >> 5, n0 = (q & 31) * 4;
        float4 wv = ((const float4*)W)[q];
        Bs[(n0 + 0) * HP + k] = __float2half_rn(wv.x);
        Bs[(n0 + 1) * HP + k] = __float2half_rn(wv.y);
        Bs[(n0 + 2) * HP + k] = __float2half_rn(wv.z);
        Bs[(n0 + 3) * HP + k] = __float2half_rn(wv.w);
    }
    __syncthreads();

    int warp_m = w >> 1;          // 0..3
    int warp_n = w & 1;           // 0..1
    int g = lane >> 2;            // 0..7
    int tg = lane & 3;            // 0..3

    float acc[2][8][4];
    #pragma unroll
    for (int mi = 0; mi < 2; mi++)
        #pragma unroll
        for (int ni = 0; ni < 8; ni++)
            #pragma unroll
            for (int c = 0; c < 4; c++) acc[mi][ni][c] = 0.f;

    #pragma unroll
    for (int kc = 0; kc < 8; kc++) {
        int k0 = kc * 16;
        uint32_t a[2][4];
        #pragma unroll
        for (int mi = 0; mi < 2; mi++) {
            int r = warp_m * 32 + mi * 16 + g;
            a[mi][0] = *(uint32_t*)&As[r * HP + k0 + 2 * tg];
            a[mi][1] = *(uint32_t*)&As[(r + 8) * HP + k0 + 2 * tg];
            a[mi][2] = *(uint32_t*)&As[r * HP + k0 + 2 * tg + 8];
            a[mi][3] = *(uint32_t*)&As[(r + 8) * HP + k0 + 2 * tg + 8];
        }
        #pragma unroll
        for (int ni = 0; ni < 8; ni++) {
            int n = warp_n * 64 + ni * 8 + g;
            uint32_t b0 = *(uint32_t*)&Bs[n * HP + k0 + 2 * tg];
            uint32_t b1 = *(uint32_t*)&Bs[n * HP + k0 + 2 * tg + 8];
            #pragma unroll
            for (int mi = 0; mi < 2; mi++) {
                asm volatile(
                    "mma.sync.aligned.m16n8k16.row.col.f32.f16.f16.f32 "
                    "{%0,%1,%2,%3}, {%4,%5,%6,%7}, {%8,%9}, {%0,%1,%2,%3};"
                    : "+f"(acc[mi][ni][0]), "+f"(acc[mi][ni][1]),
                      "+f"(acc[mi][ni][2]), "+f"(acc[mi][ni][3])
                    : "r"(a[mi][0]), "r"(a[mi][1]), "r"(a[mi][2]), "r"(a[mi][3]),
                      "r"(b0), "r"(b1));
            }
        }
    }

    // epilogue: bias + relu; half for inter-layer, float for final
    #pragma unroll
    for (int ni = 0; ni < 8; ni++) {
        int col = warp_n * 64 + ni * 8 + 2 * tg;
        float b0 = bias[col], b1 = bias[col + 1];
        #pragma unroll
        for (int mi = 0; mi < 2; mi++) {
            int row = m0 + warp_m * 32 + mi * 16 + g;
            float v00 = fmaxf(acc[mi][ni][0] + b0, 0.f);
            float v01 = fmaxf(acc[mi][ni][1] + b1, 0.f);
            float v10 = fmaxf(acc[mi][ni][2] + b0, 0.f);
            float v11 = fmaxf(acc[mi][ni][3] + b1, 0.f);
            if (out_f) {
                if (row < NN)     { float2 r0 = {v00, v01}; *(float2*)&out_f[(size_t)row * DD + col] = r0; }
                if (row + 8 < NN) { float2 r1 = {v10, v11}; *(float2*)&out_f[(size_t)(row + 8) * DD + col] = r1; }
            } else {
                if (row < NN)     *(__half2*)&hout_h[(size_t)row * DD + col] = __floats2half2_rn(v00, v01);
                if (row + 8 < NN) *(__half2*)&hout_h[(size_t)(row + 8) * DD + col] = __floats2half2_rn(v10, v11);
            }
        }
    }
}

// ---------------- launcher ----------------
extern "C" void kernel_launch(void* const* d_in, const int* in_sizes, int n_in,
                              void* d_out, int out_size) {
    const int*   ann = (const int*)d_in[0];
    const int*   src = (const int*)d_in[1];
    const int*   dst = (const int*)d_in[2];
    const float* emb = (const float*)d_in[3];
    const float* Ws  = (const float*)d_in[4];
    const float* bs  = (const float*)d_in[5];
    float*       out = (float*)d_out;

    cudaFuncSetAttribute(k_mma, cudaFuncAttributeMaxDynamicSharedMemorySize, GSMEM);

    __half* hA; __half* hB;
    cudaGetSymbolAddress((void**)&hA, g_hA);
    cudaGetSymbolAddress((void**)&hB, g_hB);

    int grid = (NN + 127) / 128;  // 782

    k_setup  <<<(NN * 32 + 255) / 256, 256>>>(ann, emb, dst);   // launch 1
    k_scan   <<<1, 1024>>>();                                   // launch 2
    k_scatter<<<(NE + 255) / 256, 256>>>(src, dst);             // launch 3
    k_sage   <<<(NN * 32 + 255) / 256, 256>>>(hA);              // launch 4  <- profiled slot
    k_mma    <<<grid, 256, GSMEM>>>(hB, nullptr, Ws + 0 * DD * DD, bs + 0 * DD);
    k_sage   <<<(NN * 32 + 255) / 256, 256>>>(hB);
    k_mma    <<<grid, 256, GSMEM>>>(hA, nullptr, Ws + 1 * DD * DD, bs + 1 * DD);
    k_sage   <<<(NN * 32 + 255) / 256, 256>>>(hA);
    k_mma    <<<grid, 256, GSMEM>>>(nullptr, out, Ws + 2 * DD * DD, bs + 2 * DD);
}

// round 7
// speedup vs baseline: 2.4911x; 2.4495x over previous
#include <cuda_runtime.h>
#include <cuda_fp16.h>
#include <cstdint>

#define NN 100000
#define NE 1600000
#define DD 128
#define LL 3
#define SCAN_BLOCKS ((NN + 1023) / 1024)   // 98

// ---------------- device scratch ----------------
__device__ __half   g_hA[(size_t)NN * DD];
__device__ __half   g_hB[(size_t)NN * DD];
__device__ __half   g_S[(size_t)NN * DD];      // aggregated features (fp16)
__device__ __half   g_WT[(size_t)LL * DD * DD]; // W transposed, half: WT[l][n][k]
__device__ float    g_inv[NN];
__device__ int      g_deg[NN];                 // zeroed at start; re-zeroed by k_scan2
__device__ int      g_pre[NN];                 // per-block inclusive prefix
__device__ int      g_bsum[SCAN_BLOCKS];
__device__ int      g_off[NN + 1];
__device__ int      g_cur[NN];
__device__ int      g_csr[NE];

// ---------------- W transpose+convert: WT[l][n][k] = (half)W[l][k][n] ----------------
__global__ void k_wconv(const float* __restrict__ Ws) {
    int t = blockIdx.x * blockDim.x + threadIdx.x;
    if (t < LL * DD * DD) {
        int l = t >> 14;
        int r = t & 16383;
        int n = r >> 7;
        int k = r & 127;
        g_WT[t] = __float2half_rn(Ws[l * DD * DD + k * DD + n]);
    }
}

// ---------------- setup: hA = (half)emb[annotation] + degree count ----------------
__global__ void k_setup(const int* __restrict__ ann, const float* __restrict__ emb,
                        const int* __restrict__ dst) {
    int t = blockIdx.x * blockDim.x + threadIdx.x;
    if (t < NN * 32) {
        int v = t >> 5, q = t & 31;
        int a = ann[v];
        float4 val = ((const float4*)emb)[(size_t)a * 32 + q];
        uint2 o;
        __half2 h01 = __floats2half2_rn(val.x, val.y);
        __half2 h23 = __floats2half2_rn(val.z, val.w);
        o.x = *(uint32_t*)&h01; o.y = *(uint32_t*)&h23;
        ((uint2*)g_hA)[t] = o;
    }
    if (t < NE) atomicAdd(&g_deg[dst[t]], 1);
}

// ---------------- scan pass 1: per-block inclusive scan + block sums ----------------
__global__ void __launch_bounds__(1024) k_scan1() {
    int t = threadIdx.x, b = blockIdx.x;
    int i = b * 1024 + t;
    int d = (i < NN) ? g_deg[i] : 0;

    int lane = t & 31, w = t >> 5;
    int v = d;
    #pragma unroll
    for (int o = 1; o < 32; o <<= 1) {
        int u = __shfl_up_sync(0xffffffffu, v, o);
        if (lane >= o) v += u;
    }
    __shared__ int ws[32];
    if (lane == 31) ws[w] = v;
    __syncthreads();
    if (w == 0) {
        int x = ws[lane];
        #pragma unroll
        for (int o = 1; o < 32; o <<= 1) {
            int u = __shfl_up_sync(0xffffffffu, x, o);
            if (lane >= o) x += u;
        }
        ws[lane] = x;
    }
    __syncthreads();
    int incl = v + (w > 0 ? ws[w - 1] : 0);
    if (i < NN) g_pre[i] = incl;
    if (t == 1023) g_bsum[b] = incl;
}

// ---------------- scan pass 2: add block offsets, emit off/cur/inv, re-zero deg ----------------
__global__ void __launch_bounds__(1024) k_scan2() {
    int t = threadIdx.x, b = blockIdx.x;
    int off = 0;
    for (int j = 0; j < b; j++) off += g_bsum[j];   // broadcast reads, <=97
    int i = b * 1024 + t;
    if (i < NN) {
        int incl = g_pre[i] + off;
        int d = g_deg[i];
        int ex = incl - d;
        g_off[i] = ex;
        g_cur[i] = ex;
        g_inv[i] = 1.0f / (float)(d + 1);
        g_deg[i] = 0;                                // restore for next replay
        if (i == NN - 1) g_off[NN] = incl;
    }
}

// ---------------- scatter edges into CSR ----------------
__global__ void k_scatter(const int* __restrict__ src, const int* __restrict__ dst) {
    int e = blockIdx.x * blockDim.x + threadIdx.x;
    if (e < NE) {
        int d = dst[e];
        int p = atomicAdd(&g_cur[d], 1);
        g_csr[p] = src[e];
    }
}

// ---------------- SAGE aggregation: warp per node, fp16 in/out, fp32 accum ----------------
__global__ void __launch_bounds__(256) k_sage(const __half* __restrict__ hin) {
    int gt = blockIdx.x * blockDim.x + threadIdx.x;
    int v = gt >> 5;
    if (v >= NN) return;
    int lane = gt & 31;
    const uint2* h2 = (const uint2*)hin;

    uint2 sv = h2[(size_t)v * 32 + lane];
    float2 f01 = __half22float2(*(__half2*)&sv.x);
    float2 f23 = __half22float2(*(__half2*)&sv.y);
    float4 acc = make_float4(f01.x, f01.y, f23.x, f23.y);

    int s = g_off[v], e = g_off[v + 1];
    for (int i = s; i < e; i++) {
        int u = __ldg(&g_csr[i]);
        uint2 xv = h2[(size_t)u * 32 + lane];
        float2 x01 = __half22float2(*(__half2*)&xv.x);
        float2 x23 = __half22float2(*(__half2*)&xv.y);
        acc.x += x01.x; acc.y += x01.y; acc.z += x23.x; acc.w += x23.y;
    }
    float iv = g_inv[v];
    uint2 r;
    __half2 r01 = __floats2half2_rn(acc.x * iv, acc.y * iv);
    __half2 r23 = __floats2half2_rn(acc.z * iv, acc.w * iv);
    r.x = *(uint32_t*)&r01; r.y = *(uint32_t*)&r23;
    ((uint2*)g_S)[(size_t)v * 32 + lane] = r;
}

// ---------------- fp16 MMA GEMM: hout = relu(S @ W + b) ----------------
// As: [128 m][HP halves] (k contiguous); Bs: [128 n][HP halves] (k contiguous, from g_WT)
#define HP 136
#define GSMEM (2 * 128 * HP * 2)

__global__ void __launch_bounds__(256, 2) k_mma(__half* __restrict__ hout_h,
                                                float* __restrict__ out_f,
                                                const __half* __restrict__ WT,
                                                const float* __restrict__ bias) {
    extern __shared__ __half sm[];
    __half* As = sm;             // [128][HP]
    __half* Bs = sm + 128 * HP;  // [128][HP]
    int tid = threadIdx.x;
    int lane = tid & 31, w = tid >> 5;
    int m0 = blockIdx.x * 128;

    // fill A and B: 2048 uint4 each (8 halves per uint4)
    #pragma unroll
    for (int t = 0; t < 8; t++) {
        int q = tid + t * 256;            // 0..2047
        int r = q >> 4, c8 = (q & 15) * 8;
        uint4 av;
        if (m0 + r < NN) av = ((const uint4*)g_S)[(size_t)(m0 + r) * 16 + (q & 15)];
        else             av = make_uint4(0u, 0u, 0u, 0u);
        *(uint4*)&As[r * HP + c8] = av;
        *(uint4*)&Bs[r * HP + c8] = ((const uint4*)WT)[q];
    }
    __syncthreads();

    int warp_m = w >> 1;          // 0..3
    int warp_n = w & 1;           // 0..1
    int g = lane >> 2;            // 0..7
    int tg = lane & 3;            // 0..3

    float acc[2][8][4];
    #pragma unroll
    for (int mi = 0; mi < 2; mi++)
        #pragma unroll
        for (int ni = 0; ni < 8; ni++)
            #pragma unroll
            for (int c = 0; c < 4; c++) acc[mi][ni][c] = 0.f;

    #pragma unroll
    for (int kc = 0; kc < 8; kc++) {
        int k0 = kc * 16;
        uint32_t a[2][4];
        #pragma unroll
        for (int mi = 0; mi < 2; mi++) {
            int r = warp_m * 32 + mi * 16 + g;
            a[mi][0] = *(uint32_t*)&As[r * HP + k0 + 2 * tg];
            a[mi][1] = *(uint32_t*)&As[(r + 8) * HP + k0 + 2 * tg];
            a[mi][2] = *(uint32_t*)&As[r * HP + k0 + 2 * tg + 8];
            a[mi][3] = *(uint32_t*)&As[(r + 8) * HP + k0 + 2 * tg + 8];
        }
        #pragma unroll
        for (int ni = 0; ni < 8; ni++) {
            int n = warp_n * 64 + ni * 8 + g;
            uint32_t b0 = *(uint32_t*)&Bs[n * HP + k0 + 2 * tg];
            uint32_t b1 = *(uint32_t*)&Bs[n * HP + k0 + 2 * tg + 8];
            #pragma unroll
            for (int mi = 0; mi < 2; mi++) {
                asm volatile(
                    "mma.sync.aligned.m16n8k16.row.col.f32.f16.f16.f32 "
                    "{%0,%1,%2,%3}, {%4,%5,%6,%7}, {%8,%9}, {%0,%1,%2,%3};"
                    : "+f"(acc[mi][ni][0]), "+f"(acc[mi][ni][1]),
                      "+f"(acc[mi][ni][2]), "+f"(acc[mi][ni][3])
                    : "r"(a[mi][0]), "r"(a[mi][1]), "r"(a[mi][2]), "r"(a[mi][3]),
                      "r"(b0), "r"(b1));
            }
        }
    }

    // epilogue: bias + relu; half for inter-layer, float for final
    #pragma unroll
    for (int ni = 0; ni < 8; ni++) {
        int col = warp_n * 64 + ni * 8 + 2 * tg;
        float b0 = bias[col], b1 = bias[col + 1];
        #pragma unroll
        for (int mi = 0; mi < 2; mi++) {
            int row = m0 + warp_m * 32 + mi * 16 + g;
            float v00 = fmaxf(acc[mi][ni][0] + b0, 0.f);
            float v01 = fmaxf(acc[mi][ni][1] + b1, 0.f);
            float v10 = fmaxf(acc[mi][ni][2] + b0, 0.f);
            float v11 = fmaxf(acc[mi][ni][3] + b1, 0.f);
            if (out_f) {
                if (row < NN)     { float2 r0 = {v00, v01}; *(float2*)&out_f[(size_t)row * DD + col] = r0; }
                if (row + 8 < NN) { float2 r1 = {v10, v11}; *(float2*)&out_f[(size_t)(row + 8) * DD + col] = r1; }
            } else {
                if (row < NN)     *(__half2*)&hout_h[(size_t)row * DD + col] = __floats2half2_rn(v00, v01);
                if (row + 8 < NN) *(__half2*)&hout_h[(size_t)(row + 8) * DD + col] = __floats2half2_rn(v10, v11);
            }
        }
    }
}

// ---------------- launcher ----------------
extern "C" void kernel_launch(void* const* d_in, const int* in_sizes, int n_in,
                              void* d_out, int out_size) {
    const int*   ann = (const int*)d_in[0];
    const int*   src = (const int*)d_in[1];
    const int*   dst = (const int*)d_in[2];
    const float* emb = (const float*)d_in[3];
    const float* Ws  = (const float*)d_in[4];
    const float* bs  = (const float*)d_in[5];
    float*       out = (float*)d_out;

    cudaFuncSetAttribute(k_mma, cudaFuncAttributeMaxDynamicSharedMemorySize, GSMEM);

    __half* hA; __half* hB; __half* WT;
    cudaGetSymbolAddress((void**)&hA, g_hA);
    cudaGetSymbolAddress((void**)&hB, g_hB);
    cudaGetSymbolAddress((void**)&WT, g_WT);

    int grid = (NN + 127) / 128;  // 782

    k_wconv  <<<(LL * DD * DD + 255) / 256, 256>>>(Ws);        // 1
    k_setup  <<<(NN * 32 + 255) / 256, 256>>>(ann, emb, dst);  // 2
    k_scan1  <<<SCAN_BLOCKS, 1024>>>();                        // 3
    k_scan2  <<<SCAN_BLOCKS, 1024>>>();                        // 4  <- profiled slot
    k_scatter<<<(NE + 255) / 256, 256>>>(src, dst);            // 5
    k_sage   <<<(NN * 32 + 255) / 256, 256>>>(hA);
    k_mma    <<<grid, 256, GSMEM>>>(hB, nullptr, WT + 0 * DD * DD, bs + 0 * DD);
    k_sage   <<<(NN * 32 + 255) / 256, 256>>>(hB);
    k_mma    <<<grid, 256, GSMEM>>>(hA, nullptr, WT + 1 * DD * DD, bs + 1 * DD);
    k_sage   <<<(NN * 32 + 255) / 256, 256>>>(hA);
    k_mma    <<<grid, 256, GSMEM>>>(nullptr, out, WT + 2 * DD * DD, bs + 2 * DD);
}

// round 8
// speedup vs baseline: 2.5389x; 1.0192x over previous
#include <cuda_runtime.h>
#include <cuda_fp16.h>
#include <cstdint>

#define NN 100000
#define NE 1600000
#define DD 128
#define LL 3
#define SCAN_BLOCKS ((NN + 1023) / 1024)   // 98

// ---------------- device scratch ----------------
__device__ __half   g_hA[(size_t)NN * DD];
__device__ __half   g_hB[(size_t)NN * DD];
__device__ __half   g_S[(size_t)NN * DD];       // aggregated features (fp16)
__device__ __half   g_WT[(size_t)LL * DD * DD];  // WT[l][n][k] = (half)W[l][k][n]
__device__ float    g_inv[NN];
__device__ int      g_deg[NN];                  // zeroed at start; re-zeroed by scan
__device__ int      g_bsum[SCAN_BLOCKS];        // value-as-flag; -1 = not ready (set by k_setup)
__device__ int      g_off[NN + 1];
__device__ int      g_cur[NN];
__device__ int      g_csr[NE];

// ---------------- setup: emb gather + degree count + wconv + bsum sentinel ----------------
__global__ void k_setup(const int* __restrict__ ann, const float* __restrict__ emb,
                        const int* __restrict__ dst, const float* __restrict__ Ws) {
    int t = blockIdx.x * blockDim.x + threadIdx.x;
    if (t < NN * 32) {
        int v = t >> 5, q = t & 31;
        int a = ann[v];
        float4 val = ((const float4*)emb)[(size_t)a * 32 + q];
        uint2 o;
        __half2 h01 = __floats2half2_rn(val.x, val.y);
        __half2 h23 = __floats2half2_rn(val.z, val.w);
        o.x = *(uint32_t*)&h01; o.y = *(uint32_t*)&h23;
        ((uint2*)g_hA)[t] = o;
    }
    if (t < NE) atomicAdd(&g_deg[dst[t]], 1);
    if (t < LL * DD * DD) {
        int l = t >> 14, r = t & 16383, n = r >> 7, k = r & 127;
        g_WT[t] = __float2half_rn(Ws[l * DD * DD + k * DD + n]);
    }
    if (t < SCAN_BLOCKS) g_bsum[t] = -1;
}

// ---------------- fused scan: block scan + decoupled aggregate lookback ----------------
__global__ void __launch_bounds__(1024) k_scan() {
    int t = threadIdx.x, b = blockIdx.x;
    int i = b * 1024 + t;
    int d = (i < NN) ? g_deg[i] : 0;

    int lane = t & 31, w = t >> 5;
    int v = d;
    #pragma unroll
    for (int o = 1; o < 32; o <<= 1) {
        int u = __shfl_up_sync(0xffffffffu, v, o);
        if (lane >= o) v += u;
    }
    __shared__ int ws[32];
    __shared__ int s_off;
    if (t == 0) s_off = 0;
    if (lane == 31) ws[w] = v;
    __syncthreads();
    if (w == 0) {
        int x = ws[lane];
        #pragma unroll
        for (int o = 1; o < 32; o <<= 1) {
            int u = __shfl_up_sync(0xffffffffu, x, o);
            if (lane >= o) x += u;
        }
        ws[lane] = x;
    }
    __syncthreads();
    int incl = v + (w > 0 ? ws[w - 1] : 0);

    // publish this block's total (value-as-flag; all blocks resident, publisher warp never polls)
    if (t == 1023) atomicExch(&g_bsum[b], incl);

    // lookback: threads t<b poll predecessor aggregates, accumulate into s_off
    if (t < b) {
        volatile int* p = &g_bsum[t];
        int val;
        do { val = *p; } while (val < 0);
        atomicAdd_block(&s_off, val);
    }
    __syncthreads();
    int off = s_off;

    if (i < NN) {
        int tot = incl + off;
        int ex = tot - d;
        g_off[i] = ex;
        g_cur[i] = ex;
        g_inv[i] = 1.0f / (float)(d + 1);
        g_deg[i] = 0;                    // restore for next replay
        if (i == NN - 1) g_off[NN] = tot;
    }
}

// ---------------- scatter edges into CSR ----------------
__global__ void k_scatter(const int* __restrict__ src, const int* __restrict__ dst) {
    int e = blockIdx.x * blockDim.x + threadIdx.x;
    if (e < NE) {
        int d = dst[e];
        int p = atomicAdd(&g_cur[d], 1);
        g_csr[p] = src[e];
    }
}

// ---------------- SAGE aggregation: warp per node ----------------
// HALFACC: pairwise half2 accumulation of 4-edge batches (safe for non-negative inputs),
// else exact fp32 accumulation. Tail edges always fp32.
template<bool HALFACC>
__global__ void __launch_bounds__(256) k_sage(const __half* __restrict__ hin) {
    int gt = blockIdx.x * blockDim.x + threadIdx.x;
    int v = gt >> 5;
    if (v >= NN) return;
    int lane = gt & 31;
    const uint2* h2 = (const uint2*)hin;

    uint2 sv = h2[(size_t)v * 32 + lane];
    float2 f01 = __half22float2(*(__half2*)&sv.x);
    float2 f23 = __half22float2(*(__half2*)&sv.y);
    float4 acc = make_float4(f01.x, f01.y, f23.x, f23.y);

    int s = g_off[v], e = g_off[v + 1];
    int i = s;
    for (; i + 4 <= e; i += 4) {
        int u0 = __ldg(&g_csr[i + 0]);
        int u1 = __ldg(&g_csr[i + 1]);
        int u2 = __ldg(&g_csr[i + 2]);
        int u3 = __ldg(&g_csr[i + 3]);
        uint2 x0 = h2[(size_t)u0 * 32 + lane];
        uint2 x1 = h2[(size_t)u1 * 32 + lane];
        uint2 x2 = h2[(size_t)u2 * 32 + lane];
        uint2 x3 = h2[(size_t)u3 * 32 + lane];
        if (HALFACC) {
            __half2 elo = __hadd2(__hadd2(*(__half2*)&x0.x, *(__half2*)&x1.x),
                                  __hadd2(*(__half2*)&x2.x, *(__half2*)&x3.x));
            __half2 ehi = __hadd2(__hadd2(*(__half2*)&x0.y, *(__half2*)&x1.y),
                                  __hadd2(*(__half2*)&x2.y, *(__half2*)&x3.y));
            float2 flo = __half22float2(elo);
            float2 fhi = __half22float2(ehi);
            acc.x += flo.x; acc.y += flo.y; acc.z += fhi.x; acc.w += fhi.y;
        } else {
            float2 a0 = __half22float2(*(__half2*)&x0.x), b0 = __half22float2(*(__half2*)&x0.y);
            float2 a1 = __half22float2(*(__half2*)&x1.x), b1 = __half22float2(*(__half2*)&x1.y);
            float2 a2 = __half22float2(*(__half2*)&x2.x), b2 = __half22float2(*(__half2*)&x2.y);
            float2 a3 = __half22float2(*(__half2*)&x3.x), b3 = __half22float2(*(__half2*)&x3.y);
            acc.x += (a0.x + a1.x) + (a2.x + a3.x);
            acc.y += (a0.y + a1.y) + (a2.y + a3.y);
            acc.z += (b0.x + b1.x) + (b2.x + b3.x);
            acc.w += (b0.y + b1.y) + (b2.y + b3.y);
        }
    }
    for (; i < e; i++) {
        int u = __ldg(&g_csr[i]);
        uint2 xv = h2[(size_t)u * 32 + lane];
        float2 x01 = __half22float2(*(__half2*)&xv.x);
        float2 x23 = __half22float2(*(__half2*)&xv.y);
        acc.x += x01.x; acc.y += x01.y; acc.z += x23.x; acc.w += x23.y;
    }

    float iv = g_inv[v];
    uint2 r;
    __half2 r01 = __floats2half2_rn(acc.x * iv, acc.y * iv);
    __half2 r23 = __floats2half2_rn(acc.z * iv, acc.w * iv);
    r.x = *(uint32_t*)&r01; r.y = *(uint32_t*)&r23;
    ((uint2*)g_S)[(size_t)v * 32 + lane] = r;
}

// ---------------- fp16 MMA GEMM: hout = relu(S @ W + b) ----------------
#define HP 136
#define GSMEM (2 * 128 * HP * 2)

__global__ void __launch_bounds__(256, 2) k_mma(__half* __restrict__ hout_h,
                                                float* __restrict__ out_f,
                                                const __half* __restrict__ WT,
                                                const float* __restrict__ bias) {
    extern __shared__ __half sm[];
    __half* As = sm;             // [128][HP]
    __half* Bs = sm + 128 * HP;  // [128][HP]
    int tid = threadIdx.x;
    int lane = tid & 31, w = tid >> 5;
    int m0 = blockIdx.x * 128;

    #pragma unroll
    for (int t = 0; t < 8; t++) {
        int q = tid + t * 256;            // 0..2047
        int r = q >> 4, c8 = (q & 15) * 8;
        uint4 av;
        if (m0 + r < NN) av = ((const uint4*)g_S)[(size_t)(m0 + r) * 16 + (q & 15)];
        else             av = make_uint4(0u, 0u, 0u, 0u);
        *(uint4*)&As[r * HP + c8] = av;
        *(uint4*)&Bs[r * HP + c8] = ((const uint4*)WT)[q];
    }
    __syncthreads();

    int warp_m = w >> 1;
    int warp_n = w & 1;
    int g = lane >> 2;
    int tg = lane & 3;

    float acc[2][8][4];
    #pragma unroll
    for (int mi = 0; mi < 2; mi++)
        #pragma unroll
        for (int ni = 0; ni < 8; ni++)
            #pragma unroll
            for (int c = 0; c < 4; c++) acc[mi][ni][c] = 0.f;

    #pragma unroll
    for (int kc = 0; kc < 8; kc++) {
        int k0 = kc * 16;
        uint32_t a[2][4];
        #pragma unroll
        for (int mi = 0; mi < 2; mi++) {
            int r = warp_m * 32 + mi * 16 + g;
            a[mi][0] = *(uint32_t*)&As[r * HP + k0 + 2 * tg];
            a[mi][1] = *(uint32_t*)&As[(r + 8) * HP + k0 + 2 * tg];
            a[mi][2] = *(uint32_t*)&As[r * HP + k0 + 2 * tg + 8];
            a[mi][3] = *(uint32_t*)&As[(r + 8) * HP + k0 + 2 * tg + 8];
        }
        #pragma unroll
        for (int ni = 0; ni < 8; ni++) {
            int n = warp_n * 64 + ni * 8 + g;
            uint32_t b0 = *(uint32_t*)&Bs[n * HP + k0 + 2 * tg];
            uint32_t b1 = *(uint32_t*)&Bs[n * HP + k0 + 2 * tg + 8];
            #pragma unroll
            for (int mi = 0; mi < 2; mi++) {
                asm volatile(
                    "mma.sync.aligned.m16n8k16.row.col.f32.f16.f16.f32 "
                    "{%0,%1,%2,%3}, {%4,%5,%6,%7}, {%8,%9}, {%0,%1,%2,%3};"
                    : "+f"(acc[mi][ni][0]), "+f"(acc[mi][ni][1]),
                      "+f"(acc[mi][ni][2]), "+f"(acc[mi][ni][3])
                    : "r"(a[mi][0]), "r"(a[mi][1]), "r"(a[mi][2]), "r"(a[mi][3]),
                      "r"(b0), "r"(b1));
            }
        }
    }

    #pragma unroll
    for (int ni = 0; ni < 8; ni++) {
        int col = warp_n * 64 + ni * 8 + 2 * tg;
        float b0 = bias[col], b1 = bias[col + 1];
        #pragma unroll
        for (int mi = 0; mi < 2; mi++) {
            int row = m0 + warp_m * 32 + mi * 16 + g;
            float v00 = fmaxf(acc[mi][ni][0] + b0, 0.f);
            float v01 = fmaxf(acc[mi][ni][1] + b1, 0.f);
            float v10 = fmaxf(acc[mi][ni][2] + b0, 0.f);
            float v11 = fmaxf(acc[mi][ni][3] + b1, 0.f);
            if (out_f) {
                if (row < NN)     { float2 r0 = {v00, v01}; *(float2*)&out_f[(size_t)row * DD + col] = r0; }
                if (row + 8 < NN) { float2 r1 = {v10, v11}; *(float2*)&out_f[(size_t)(row + 8) * DD + col] = r1; }
            } else {
                if (row < NN)     *(__half2*)&hout_h[(size_t)row * DD + col] = __floats2half2_rn(v00, v01);
                if (row + 8 < NN) *(__half2*)&hout_h[(size_t)(row + 8) * DD + col] = __floats2half2_rn(v10, v11);
            }
        }
    }
}

// ---------------- launcher ----------------
extern "C" void kernel_launch(void* const* d_in, const int* in_sizes, int n_in,
                              void* d_out, int out_size) {
    const int*   ann = (const int*)d_in[0];
    const int*   src = (const int*)d_in[1];
    const int*   dst = (const int*)d_in[2];
    const float* emb = (const float*)d_in[3];
    const float* Ws  = (const float*)d_in[4];
    const float* bs  = (const float*)d_in[5];
    float*       out = (float*)d_out;

    cudaFuncSetAttribute(k_mma, cudaFuncAttributeMaxDynamicSharedMemorySize, GSMEM);

    __half* hA; __half* hB; __half* WT;
    cudaGetSymbolAddress((void**)&hA, g_hA);
    cudaGetSymbolAddress((void**)&hB, g_hB);
    cudaGetSymbolAddress((void**)&WT, g_WT);

    int grid = (NN + 127) / 128;  // 782

    k_setup      <<<(NN * 32 + 255) / 256, 256>>>(ann, emb, dst, Ws);  // 1
    k_scan       <<<SCAN_BLOCKS, 1024>>>();                            // 2
    k_scatter    <<<(NE + 255) / 256, 256>>>(src, dst);                // 3
    k_sage<false><<<(NN * 32 + 255) / 256, 256>>>(hA);                 // 4 <- profiled (fp32-acc, signed input)
    k_mma        <<<grid, 256, GSMEM>>>(hB, nullptr, WT + 0 * DD * DD, bs + 0 * DD);
    k_sage<true> <<<(NN * 32 + 255) / 256, 256>>>(hB);                 // relu inputs: half pairwise OK
    k_mma        <<<grid, 256, GSMEM>>>(hA, nullptr, WT + 1 * DD * DD, bs + 1 * DD);
    k_sage<true> <<<(NN * 32 + 255) / 256, 256>>>(hA);
    k_mma        <<<grid, 256, GSMEM>>>(nullptr, out, WT + 2 * DD * DD, bs + 2 * DD);
}

// round 10
// speedup vs baseline: 2.5587x; 1.0078x over previous
#include <cuda_runtime.h>
#include <cuda_fp16.h>
#include <cstdint>

#define NN 100000
#define NE 1600000
#define DD 128
#define LL 3
#define SCAN_BLOCKS ((NN + 1023) / 1024)   // 98

// ---------------- device scratch ----------------
__device__ __half   g_hA[(size_t)NN * DD];
__device__ __half   g_hB[(size_t)NN * DD];
__device__ __half   g_S[(size_t)NN * DD];       // aggregated features (fp16)
__device__ __half   g_WT[(size_t)LL * DD * DD];  // WT[l][n][k] = (half)W[l][k][n]
__device__ float    g_inv[NN];
__device__ int      g_deg[NN];                  // zeroed at start; re-zeroed by scan
__device__ int      g_bsum[SCAN_BLOCKS];        // value-as-flag; -1 = not ready
__device__ int      g_off[NN + 1];
__device__ int      g_cur[NN];
__device__ int      g_csr[NE];

// ---------------- setup: emb gather + degree count + wconv + bsum sentinel ----------------
__global__ void k_setup(const int* __restrict__ ann, const float* __restrict__ emb,
                        const int* __restrict__ dst, const float* __restrict__ Ws) {
    int t = blockIdx.x * blockDim.x + threadIdx.x;
    if (t < NN * 32) {
        int v = t >> 5, q = t & 31;
        int a = ann[v];
        float4 val = ((const float4*)emb)[(size_t)a * 32 + q];
        uint2 o;
        __half2 h01 = __floats2half2_rn(val.x, val.y);
        __half2 h23 = __floats2half2_rn(val.z, val.w);
        o.x = *(uint32_t*)&h01; o.y = *(uint32_t*)&h23;
        ((uint2*)g_hA)[t] = o;
    }
    if (t < NE) atomicAdd(&g_deg[dst[t]], 1);
    if (t < LL * DD * DD) {
        int l = t >> 14, r = t & 16383, n = r >> 7, k = r & 127;
        g_WT[t] = __float2half_rn(Ws[l * DD * DD + k * DD + n]);
    }
    if (t < SCAN_BLOCKS) g_bsum[t] = -1;
}

// ---------------- fused scan: block scan + aggregate lookback ----------------
__global__ void __launch_bounds__(1024) k_scan() {
    int t = threadIdx.x, b = blockIdx.x;
    int i = b * 1024 + t;
    int d = (i < NN) ? g_deg[i] : 0;

    int lane = t & 31, w = t >> 5;
    int v = d;
    #pragma unroll
    for (int o = 1; o < 32; o <<= 1) {
        int u = __shfl_up_sync(0xffffffffu, v, o);
        if (lane >= o) v += u;
    }
    __shared__ int ws[32];
    __shared__ int s_off;
    if (t == 0) s_off = 0;
    if (lane == 31) ws[w] = v;
    __syncthreads();
    if (w == 0) {
        int x = ws[lane];
        #pragma unroll
        for (int o = 1; o < 32; o <<= 1) {
            int u = __shfl_up_sync(0xffffffffu, x, o);
            if (lane >= o) x += u;
        }
        ws[lane] = x;
    }
    __syncthreads();
    int incl = v + (w > 0 ? ws[w - 1] : 0);

    if (t == 1023) atomicExch(&g_bsum[b], incl);

    if (t < b) {
        volatile int* p = &g_bsum[t];
        int val;
        do { val = *p; } while (val < 0);
        atomicAdd_block(&s_off, val);
    }
    __syncthreads();
    int off = s_off;

    if (i < NN) {
        int tot = incl + off;
        int ex = tot - d;
        g_off[i] = ex;
        g_cur[i] = ex;
        g_inv[i] = 1.0f / (float)(d + 1);
        g_deg[i] = 0;
        if (i == NN - 1) g_off[NN] = tot;
    }
}

// ---------------- scatter edges into CSR (4 edges / thread, vectorized loads) ----------------
__global__ void k_scatter(const int* __restrict__ src, const int* __restrict__ dst) {
    int q = blockIdx.x * blockDim.x + threadIdx.x;
    if (q < NE / 4) {
        int4 d4 = ((const int4*)dst)[q];
        int4 s4 = ((const int4*)src)[q];
        int p0 = atomicAdd(&g_cur[d4.x], 1); g_csr[p0] = s4.x;
        int p1 = atomicAdd(&g_cur[d4.y], 1); g_csr[p1] = s4.y;
        int p2 = atomicAdd(&g_cur[d4.z], 1); g_csr[p2] = s4.z;
        int p3 = atomicAdd(&g_cur[d4.w], 1); g_csr[p3] = s4.w;
    }
}

// ---------------- SAGE aggregation: warp per node, int4 csr loads, half2 tree ----------------
__global__ void __launch_bounds__(256) k_sage(const __half* __restrict__ hin) {
    int gt = blockIdx.x * blockDim.x + threadIdx.x;
    int v = gt >> 5;
    if (v >= NN) return;
    int lane = gt & 31;
    const uint2* h2 = (const uint2*)hin;

    uint2 sv = h2[(size_t)v * 32 + lane];
    float2 f01 = __half22float2(*(__half2*)&sv.x);
    float2 f23 = __half22float2(*(__half2*)&sv.y);
    float4 acc = make_float4(f01.x, f01.y, f23.x, f23.y);

    int s = g_off[v], e = g_off[v + 1];
    int i = s;
    // prologue: reach int4 alignment
    for (; i < e && (i & 3); i++) {
        int u = __ldg(&g_csr[i]);
        uint2 xv = h2[(size_t)u * 32 + lane];
        float2 x01 = __half22float2(*(__half2*)&xv.x);
        float2 x23 = __half22float2(*(__half2*)&xv.y);
        acc.x += x01.x; acc.y += x01.y; acc.z += x23.x; acc.w += x23.y;
    }
    // main: 4 edges per iteration, one LDG.128 for indices, half2 pairwise tree
    for (; i + 4 <= e; i += 4) {
        int4 u4 = *(const int4*)(g_csr + i);
        uint2 x0 = h2[(size_t)u4.x * 32 + lane];
        uint2 x1 = h2[(size_t)u4.y * 32 + lane];
        uint2 x2 = h2[(size_t)u4.z * 32 + lane];
        uint2 x3 = h2[(size_t)u4.w * 32 + lane];
        __half2 elo = __hadd2(__hadd2(*(__half2*)&x0.x, *(__half2*)&x1.x),
                              __hadd2(*(__half2*)&x2.x, *(__half2*)&x3.x));
        __half2 ehi = __hadd2(__hadd2(*(__half2*)&x0.y, *(__half2*)&x1.y),
                              __hadd2(*(__half2*)&x2.y, *(__half2*)&x3.y));
        float2 flo = __half22float2(elo);
        float2 fhi = __half22float2(ehi);
        acc.x += flo.x; acc.y += flo.y; acc.z += fhi.x; acc.w += fhi.y;
    }
    // tail
    for (; i < e; i++) {
        int u = __ldg(&g_csr[i]);
        uint2 xv = h2[(size_t)u * 32 + lane];
        float2 x01 = __half22float2(*(__half2*)&xv.x);
        float2 x23 = __half22float2(*(__half2*)&xv.y);
        acc.x += x01.x; acc.y += x01.y; acc.z += x23.x; acc.w += x23.y;
    }

    float iv = g_inv[v];
    uint2 r;
    __half2 r01 = __floats2half2_rn(acc.x * iv, acc.y * iv);
    __half2 r23 = __floats2half2_rn(acc.z * iv, acc.w * iv);
    r.x = *(uint32_t*)&r01; r.y = *(uint32_t*)&r23;
    ((uint2*)g_S)[(size_t)v * 32 + lane] = r;
}

// ---------------- fp16 MMA GEMM: hout = relu(S @ W + b) ----------------
#define HP 136
#define GSMEM (2 * 128 * HP * 2)

__global__ void __launch_bounds__(256, 2) k_mma(__half* __restrict__ hout_h,
                                                float* __restrict__ out_f,
                                                const __half* __restrict__ WT,
                                                const float* __restrict__ bias) {
    extern __shared__ __half sm[];
    __half* As = sm;             // [128][HP]
    __half* Bs = sm + 128 * HP;  // [128][HP]
    int tid = threadIdx.x;
    int lane = tid & 31, w = tid >> 5;
    int m0 = blockIdx.x * 128;

    #pragma unroll
    for (int t = 0; t < 8; t++) {
        int q = tid + t * 256;            // 0..2047
        int r = q >> 4, c8 = (q & 15) * 8;
        uint4 av;
        if (m0 + r < NN) av = ((const uint4*)g_S)[(size_t)(m0 + r) * 16 + (q & 15)];
        else             av = make_uint4(0u, 0u, 0u, 0u);
        *(uint4*)&As[r * HP + c8] = av;
        *(uint4*)&Bs[r * HP + c8] = ((const uint4*)WT)[q];
    }
    __syncthreads();

    int warp_m = w >> 1;
    int warp_n = w & 1;
    int g = lane >> 2;
    int tg = lane & 3;

    float acc[2][8][4];
    #pragma unroll
    for (int mi = 0; mi < 2; mi++)
        #pragma unroll
        for (int ni = 0; ni < 8; ni++)
            #pragma unroll
            for (int c = 0; c < 4; c++) acc[mi][ni][c] = 0.f;

    #pragma unroll
    for (int kc = 0; kc < 8; kc++) {
        int k0 = kc * 16;
        uint32_t a[2][4];
        #pragma unroll
        for (int mi = 0; mi < 2; mi++) {
            int r = warp_m * 32 + mi * 16 + g;
            a[mi][0] = *(uint32_t*)&As[r * HP + k0 + 2 * tg];
            a[mi][1] = *(uint32_t*)&As[(r + 8) * HP + k0 + 2 * tg];
            a[mi][2] = *(uint32_t*)&As[r * HP + k0 + 2 * tg + 8];
            a[mi][3] = *(uint32_t*)&As[(r + 8) * HP + k0 + 2 * tg + 8];
        }
        #pragma unroll
        for (int ni = 0; ni < 8; ni++) {
            int n = warp_n * 64 + ni * 8 + g;
            uint32_t b0 = *(uint32_t*)&Bs[n * HP + k0 + 2 * tg];
            uint32_t b1 = *(uint32_t*)&Bs[n * HP + k0 + 2 * tg + 8];
            #pragma unroll
            for (int mi = 0; mi < 2; mi++) {
                asm volatile(
                    "mma.sync.aligned.m16n8k16.row.col.f32.f16.f16.f32 "
                    "{%0,%1,%2,%3}, {%4,%5,%6,%7}, {%8,%9}, {%0,%1,%2,%3};"
                    : "+f"(acc[mi][ni][0]), "+f"(acc[mi][ni][1]),
                      "+f"(acc[mi][ni][2]), "+f"(acc[mi][ni][3])
                    : "r"(a[mi][0]), "r"(a[mi][1]), "r"(a[mi][2]), "r"(a[mi][3]),
                      "r"(b0), "r"(b1));
            }
        }
    }

    #pragma unroll
    for (int ni = 0; ni < 8; ni++) {
        int col = warp_n * 64 + ni * 8 + 2 * tg;
        float b0 = bias[col], b1 = bias[col + 1];
        #pragma unroll
        for (int mi = 0; mi < 2; mi++) {
            int row = m0 + warp_m * 32 + mi * 16 + g;
            float v00 = fmaxf(acc[mi][ni][0] + b0, 0.f);
            float v01 = fmaxf(acc[mi][ni][1] + b1, 0.f);
            float v10 = fmaxf(acc[mi][ni][2] + b0, 0.f);
            float v11 = fmaxf(acc[mi][ni][3] + b1, 0.f);
            if (out_f) {
                if (row < NN)     { float2 r0 = {v00, v01}; *(float2*)&out_f[(size_t)row * DD + col] = r0; }
                if (row + 8 < NN) { float2 r1 = {v10, v11}; *(float2*)&out_f[(size_t)(row + 8) * DD + col] = r1; }
            } else {
                if (row < NN)     *(__half2*)&hout_h[(size_t)row * DD + col] = __floats2half2_rn(v00, v01);
                if (row + 8 < NN) *(__half2*)&hout_h[(size_t)(row + 8) * DD + col] = __floats2half2_rn(v10, v11);
            }
        }
    }
}

// ---------------- launcher ----------------
extern "C" void kernel_launch(void* const* d_in, const int* in_sizes, int n_in,
                              void* d_out, int out_size) {
    const int*   ann = (const int*)d_in[0];
    const int*   src = (const int*)d_in[1];
    const int*   dst = (const int*)d_in[2];
    const float* emb = (const float*)d_in[3];
    const float* Ws  = (const float*)d_in[4];
    const float* bs  = (const float*)d_in[5];
    float*       out = (float*)d_out;

    cudaFuncSetAttribute(k_mma, cudaFuncAttributeMaxDynamicSharedMemorySize, GSMEM);

    __half* hA; __half* hB; __half* WT;
    cudaGetSymbolAddress((void**)&hA, g_hA);
    cudaGetSymbolAddress((void**)&hB, g_hB);
    cudaGetSymbolAddress((void**)&WT, g_WT);

    int grid = (NN + 127) / 128;  // 782

    k_setup  <<<(NN * 32 + 255) / 256, 256>>>(ann, emb, dst, Ws);  // 1
    k_scan   <<<SCAN_BLOCKS, 1024>>>();                            // 2
    k_scatter<<<(NE / 4 + 255) / 256, 256>>>(src, dst);            // 3
    k_sage   <<<(NN * 32 + 255) / 256, 256>>>(hA);                 // 4 <- profiled slot
    k_mma    <<<grid, 256, GSMEM>>>(hB, nullptr, WT + 0 * DD * DD, bs + 0 * DD);
    k_sage   <<<(NN * 32 + 255) / 256, 256>>>(hB);
    k_mma    <<<grid, 256, GSMEM>>>(hA, nullptr, WT + 1 * DD * DD, bs + 1 * DD);
    k_sage   <<<(NN * 32 + 255) / 256, 256>>>(hA);
    k_mma    <<<grid, 256, GSMEM>>>(nullptr, out, WT + 2 * DD * DD, bs + 2 * DD);
}

// round 11
// speedup vs baseline: 2.6345x; 1.0296x over previous
#include <cuda_runtime.h>
#include <cuda_fp16.h>
#include <cstdint>

#define NN 100000
#define NE 1600000
#define DD 128
#define LL 3
#define SCAN_BLOCKS ((NN + 1023) / 1024)   // 98

// ---------------- device scratch ----------------
__device__ __half   g_hA[(size_t)NN * DD];
__device__ __half   g_hB[(size_t)NN * DD];
__device__ __half   g_S[(size_t)NN * DD];       // aggregated features (fp16)
__device__ __half   g_WT[(size_t)LL * DD * DD];  // WT[l][n][k] = (half)W[l][k][n]
__device__ float    g_inv[NN];
__device__ int      g_deg[NN];                  // zeroed at start; re-zeroed by scan
__device__ int      g_bsum[SCAN_BLOCKS];        // value-as-flag; -1 = not ready
__device__ int      g_off[NN + 1];
__device__ int      g_cur[NN];
__device__ int      g_csr[NE];                  // BYTE offsets (src * 256)

// ---------------- setup: emb gather + degree count + wconv + bsum sentinel ----------------
__global__ void k_setup(const int* __restrict__ ann, const float* __restrict__ emb,
                        const int* __restrict__ dst, const float* __restrict__ Ws) {
    int t = blockIdx.x * blockDim.x + threadIdx.x;
    if (t < NN * 32) {
        int v = t >> 5, q = t & 31;
        int a = ann[v];
        float4 val = ((const float4*)emb)[(size_t)a * 32 + q];
        uint2 o;
        __half2 h01 = __floats2half2_rn(val.x, val.y);
        __half2 h23 = __floats2half2_rn(val.z, val.w);
        o.x = *(uint32_t*)&h01; o.y = *(uint32_t*)&h23;
        ((uint2*)g_hA)[t] = o;
    }
    if (t < NE) atomicAdd(&g_deg[dst[t]], 1);
    if (t < LL * DD * DD) {
        int l = t >> 14, r = t & 16383, n = r >> 7, k = r & 127;
        g_WT[t] = __float2half_rn(Ws[l * DD * DD + k * DD + n]);
    }
    if (t < SCAN_BLOCKS) g_bsum[t] = -1;
}

// ---------------- fused scan: block scan + aggregate lookback ----------------
__global__ void __launch_bounds__(1024) k_scan() {
    int t = threadIdx.x, b = blockIdx.x;
    int i = b * 1024 + t;
    int d = (i < NN) ? g_deg[i] : 0;

    int lane = t & 31, w = t >> 5;
    int v = d;
    #pragma unroll
    for (int o = 1; o < 32; o <<= 1) {
        int u = __shfl_up_sync(0xffffffffu, v, o);
        if (lane >= o) v += u;
    }
    __shared__ int ws[32];
    __shared__ int s_off;
    if (t == 0) s_off = 0;
    if (lane == 31) ws[w] = v;
    __syncthreads();
    if (w == 0) {
        int x = ws[lane];
        #pragma unroll
        for (int o = 1; o < 32; o <<= 1) {
            int u = __shfl_up_sync(0xffffffffu, x, o);
            if (lane >= o) x += u;
        }
        ws[lane] = x;
    }
    __syncthreads();
    int incl = v + (w > 0 ? ws[w - 1] : 0);

    if (t == 1023) atomicExch(&g_bsum[b], incl);

    if (t < b) {
        volatile int* p = &g_bsum[t];
        int val;
        do { val = *p; } while (val < 0);
        atomicAdd_block(&s_off, val);
    }
    __syncthreads();
    int off = s_off;

    if (i < NN) {
        int tot = incl + off;
        int ex = tot - d;
        g_off[i] = ex;
        g_cur[i] = ex;
        g_inv[i] = 1.0f / (float)(d + 1);
        g_deg[i] = 0;
        if (i == NN - 1) g_off[NN] = tot;
    }
}

// ---------------- scatter: CSR stores BYTE offsets (src*256) ----------------
__global__ void k_scatter(const int* __restrict__ src, const int* __restrict__ dst) {
    int q = blockIdx.x * blockDim.x + threadIdx.x;
    if (q < NE / 4) {
        int4 d4 = ((const int4*)dst)[q];
        int4 s4 = ((const int4*)src)[q];
        int p0 = atomicAdd(&g_cur[d4.x], 1); g_csr[p0] = s4.x << 8;
        int p1 = atomicAdd(&g_cur[d4.y], 1); g_csr[p1] = s4.y << 8;
        int p2 = atomicAdd(&g_cur[d4.z], 1); g_csr[p2] = s4.z << 8;
        int p3 = atomicAdd(&g_cur[d4.w], 1); g_csr[p3] = s4.w << 8;
    }
}

// ---------------- SAGE aggregation: 2 nodes/warp, 16 lanes x uint4 per row ----------------
__global__ void __launch_bounds__(256) k_sage(const __half* __restrict__ hin) {
    int gt = blockIdx.x * blockDim.x + threadIdx.x;
    int warp = gt >> 5;
    int hh = (gt >> 4) & 1;       // half-warp id: node selector
    int sub = gt & 15;            // lane within half-warp
    int v = warp * 2 + hh;
    if (v >= NN) return;
    const char* hb = (const char*)hin + sub * 16;

    // self term
    uint4 sv = *(const uint4*)(hb + (size_t)v * 256);
    float2 s0 = __half22float2(*(__half2*)&sv.x);
    float2 s1 = __half22float2(*(__half2*)&sv.y);
    float2 s2 = __half22float2(*(__half2*)&sv.z);
    float2 s3 = __half22float2(*(__half2*)&sv.w);
    float fa0 = s0.x, fa1 = s0.y, fa2 = s1.x, fa3 = s1.y;
    float fa4 = s2.x, fa5 = s2.y, fa6 = s3.x, fa7 = s3.y;

    int s = g_off[v];
    int n = g_off[v + 1] - s;
    int nmax = max(n, __shfl_xor_sync(0xffffffffu, n, 16));

    __half2 z = __float2half2_rn(0.f);
    __half2 ha0 = z, ha1 = z, ha2 = z, ha3 = z;

    for (int j = 0; j < nmax; j++) {
        int uoff = (j < n) ? __ldg(&g_csr[s + j]) : 0;   // broadcast per half-warp
        uint4 xv = *(const uint4*)(hb + uoff);           // 2 rows per warp instruction
        if (j < n) {
            ha0 = __hadd2(ha0, *(__half2*)&xv.x);
            ha1 = __hadd2(ha1, *(__half2*)&xv.y);
            ha2 = __hadd2(ha2, *(__half2*)&xv.z);
            ha3 = __hadd2(ha3, *(__half2*)&xv.w);
        }
        if ((j & 3) == 3) {   // fold to fp32 every 4 iterations (tree depth <= 4)
            float2 g0 = __half22float2(ha0); fa0 += g0.x; fa1 += g0.y;
            float2 g1 = __half22float2(ha1); fa2 += g1.x; fa3 += g1.y;
            float2 g2 = __half22float2(ha2); fa4 += g2.x; fa5 += g2.y;
            float2 g3 = __half22float2(ha3); fa6 += g3.x; fa7 += g3.y;
            ha0 = z; ha1 = z; ha2 = z; ha3 = z;
        }
    }
    // final fold
    {
        float2 g0 = __half22float2(ha0); fa0 += g0.x; fa1 += g0.y;
        float2 g1 = __half22float2(ha1); fa2 += g1.x; fa3 += g1.y;
        float2 g2 = __half22float2(ha2); fa4 += g2.x; fa5 += g2.y;
        float2 g3 = __half22float2(ha3); fa6 += g3.x; fa7 += g3.y;
    }

    float iv = g_inv[v];
    uint4 r;
    __half2 r0 = __floats2half2_rn(fa0 * iv, fa1 * iv);
    __half2 r1 = __floats2half2_rn(fa2 * iv, fa3 * iv);
    __half2 r2 = __floats2half2_rn(fa4 * iv, fa5 * iv);
    __half2 r3 = __floats2half2_rn(fa6 * iv, fa7 * iv);
    r.x = *(uint32_t*)&r0; r.y = *(uint32_t*)&r1;
    r.z = *(uint32_t*)&r2; r.w = *(uint32_t*)&r3;
    *(uint4*)((char*)g_S + (size_t)v * 256 + sub * 16) = r;
}

// ---------------- fp16 MMA GEMM: hout = relu(S @ W + b) ----------------
#define HP 136
#define GSMEM (2 * 128 * HP * 2)

__global__ void __launch_bounds__(256, 2) k_mma(__half* __restrict__ hout_h,
                                                float* __restrict__ out_f,
                                                const __half* __restrict__ WT,
                                                const float* __restrict__ bias) {
    extern __shared__ __half sm[];
    __half* As = sm;             // [128][HP]
    __half* Bs = sm + 128 * HP;  // [128][HP]
    int tid = threadIdx.x;
    int lane = tid & 31, w = tid >> 5;
    int m0 = blockIdx.x * 128;

    #pragma unroll
    for (int t = 0; t < 8; t++) {
        int q = tid + t * 256;            // 0..2047
        int r = q >> 4, c8 = (q & 15) * 8;
        uint4 av;
        if (m0 + r < NN) av = ((const uint4*)g_S)[(size_t)(m0 + r) * 16 + (q & 15)];
        else             av = make_uint4(0u, 0u, 0u, 0u);
        *(uint4*)&As[r * HP + c8] = av;
        *(uint4*)&Bs[r * HP + c8] = ((const uint4*)WT)[q];
    }
    __syncthreads();

    int warp_m = w >> 1;
    int warp_n = w & 1;
    int g = lane >> 2;
    int tg = lane & 3;

    float acc[2][8][4];
    #pragma unroll
    for (int mi = 0; mi < 2; mi++)
        #pragma unroll
        for (int ni = 0; ni < 8; ni++)
            #pragma unroll
            for (int c = 0; c < 4; c++) acc[mi][ni][c] = 0.f;

    #pragma unroll
    for (int kc = 0; kc < 8; kc++) {
        int k0 = kc * 16;
        uint32_t a[2][4];
        #pragma unroll
        for (int mi = 0; mi < 2; mi++) {
            int r = warp_m * 32 + mi * 16 + g;
            a[mi][0] = *(uint32_t*)&As[r * HP + k0 + 2 * tg];
            a[mi][1] = *(uint32_t*)&As[(r + 8) * HP + k0 + 2 * tg];
            a[mi][2] = *(uint32_t*)&As[r * HP + k0 + 2 * tg + 8];
            a[mi][3] = *(uint32_t*)&As[(r + 8) * HP + k0 + 2 * tg + 8];
        }
        #pragma unroll
        for (int ni = 0; ni < 8; ni++) {
            int n = warp_n * 64 + ni * 8 + g;
            uint32_t b0 = *(uint32_t*)&Bs[n * HP + k0 + 2 * tg];
            uint32_t b1 = *(uint32_t*)&Bs[n * HP + k0 + 2 * tg + 8];
            #pragma unroll
            for (int mi = 0; mi < 2; mi++) {
                asm volatile(
                    "mma.sync.aligned.m16n8k16.row.col.f32.f16.f16.f32 "
                    "{%0,%1,%2,%3}, {%4,%5,%6,%7}, {%8,%9}, {%0,%1,%2,%3};"
                    : "+f"(acc[mi][ni][0]), "+f"(acc[mi][ni][1]),
                      "+f"(acc[mi][ni][2]), "+f"(acc[mi][ni][3])
                    : "r"(a[mi][0]), "r"(a[mi][1]), "r"(a[mi][2]), "r"(a[mi][3]),
                      "r"(b0), "r"(b1));
            }
        }
    }

    #pragma unroll
    for (int ni = 0; ni < 8; ni++) {
        int col = warp_n * 64 + ni * 8 + 2 * tg;
        float b0 = bias[col], b1 = bias[col + 1];
        #pragma unroll
        for (int mi = 0; mi < 2; mi++) {
            int row = m0 + warp_m * 32 + mi * 16 + g;
            float v00 = fmaxf(acc[mi][ni][0] + b0, 0.f);
            float v01 = fmaxf(acc[mi][ni][1] + b1, 0.f);
            float v10 = fmaxf(acc[mi][ni][2] + b0, 0.f);
            float v11 = fmaxf(acc[mi][ni][3] + b1, 0.f);
            if (out_f) {
                if (row < NN)     { float2 r0 = {v00, v01}; *(float2*)&out_f[(size_t)row * DD + col] = r0; }
                if (row + 8 < NN) { float2 r1 = {v10, v11}; *(float2*)&out_f[(size_t)(row + 8) * DD + col] = r1; }
            } else {
                if (row < NN)     *(__half2*)&hout_h[(size_t)row * DD + col] = __floats2half2_rn(v00, v01);
                if (row + 8 < NN) *(__half2*)&hout_h[(size_t)(row + 8) * DD + col] = __floats2half2_rn(v10, v11);
            }
        }
    }
}

// ---------------- launcher ----------------
extern "C" void kernel_launch(void* const* d_in, const int* in_sizes, int n_in,
                              void* d_out, int out_size) {
    const int*   ann = (const int*)d_in[0];
    const int*   src = (const int*)d_in[1];
    const int*   dst = (const int*)d_in[2];
    const float* emb = (const float*)d_in[3];
    const float* Ws  = (const float*)d_in[4];
    const float* bs  = (const float*)d_in[5];
    float*       out = (float*)d_out;

    cudaFuncSetAttribute(k_mma, cudaFuncAttributeMaxDynamicSharedMemorySize, GSMEM);

    __half* hA; __half* hB; __half* WT;
    cudaGetSymbolAddress((void**)&hA, g_hA);
    cudaGetSymbolAddress((void**)&hB, g_hB);
    cudaGetSymbolAddress((void**)&WT, g_WT);

    int grid = (NN + 127) / 128;          // 782 (mma)
    int sgrid = (NN / 2 * 32 + 255) / 256; // 6250 (sage: 2 nodes/warp)

    k_setup  <<<(NN * 32 + 255) / 256, 256>>>(ann, emb, dst, Ws);  // 1
    k_scan   <<<SCAN_BLOCKS, 1024>>>();                            // 2
    k_scatter<<<(NE / 4 + 255) / 256, 256>>>(src, dst);            // 3
    k_sage   <<<sgrid, 256>>>(hA);                                 // 4 <- profiled slot
    k_mma    <<<grid, 256, GSMEM>>>(hB, nullptr, WT + 0 * DD * DD, bs + 0 * DD);
    k_sage   <<<sgrid, 256>>>(hB);
    k_mma    <<<grid, 256, GSMEM>>>(hA, nullptr, WT + 1 * DD * DD, bs + 1 * DD);
    k_sage   <<<sgrid, 256>>>(hA);
    k_mma    <<<grid, 256, GSMEM>>>(nullptr, out, WT + 2 * DD * DD, bs + 2 * DD);
}